// round 9
// baseline (speedup 1.0000x reference)
#include <cuda_runtime.h>
#include <cuda_fp16.h>
#include <cuda_bf16.h>

#define N_NODES 100000
#define N_EDGES 3200000
#define E_TOT   (N_EDGES + N_NODES)
#define NEG_SLOPE 0.2f
#define N_TILES 98   // ceil(100000 / 1024)

// ---------------- device scratch (allocation-free contract) ----------------
__device__ int g_cnt[N_NODES];
__device__ int g_off[N_NODES + 1];
__device__ int g_cursor[N_NODES];
__device__ int g_csr_src[E_TOT];
__device__ int g_blk[N_TILES];

__device__ __align__(16) __half g_h1[N_NODES * 64];  // layer-1 features (half gather table)
__device__ __align__(16) float g_al1[N_NODES * 4];   // [als0, als1, ald0, ald1]
__device__ __align__(16) float g_hin2[N_NODES * 64]; // relu(layer-1 out), fp32 for matmul
__device__ __align__(16) __half g_h2[N_NODES * 64];  // layer-2 features (half gather table)
__device__ __align__(8)  float g_al2[N_NODES * 2];   // [als, ald]

// ---------------- CSR build ----------------
__global__ void k_init() {
    int i = blockIdx.x * blockDim.x + threadIdx.x;
    if (i < N_NODES) g_cnt[i] = 0;
}

__global__ void k_hist(const int* __restrict__ ei) {
    int e = blockIdx.x * blockDim.x + threadIdx.x;
    if (e < N_EDGES) atomicAdd(&g_cnt[ei[N_EDGES + e]], 1);   // dst row
}

// phase A: per-tile (1024) sums
__global__ void k_scan_a() {
    __shared__ int ws[32];
    int tid = threadIdx.x, lane = tid & 31, wid = tid >> 5;
    int i = blockIdx.x * 1024 + tid;
    int v = (i < N_NODES) ? g_cnt[i] : 0;
    #pragma unroll
    for (int d = 16; d; d >>= 1) v += __shfl_xor_sync(0xFFFFFFFFu, v, d);
    if (lane == 0) ws[wid] = v;
    __syncthreads();
    if (wid == 0) {
        int y = ws[lane];
        #pragma unroll
        for (int d = 16; d; d >>= 1) y += __shfl_xor_sync(0xFFFFFFFFu, y, d);
        if (lane == 0) g_blk[blockIdx.x] = y;
    }
}

// phase C: per-tile rescan + inline tile-offset + self-loop emission
// off[i] = exclusive_scan(cnt)[i] + i  (the +i accounts for one self-loop per
// preceding node); self-loop goes in slot off[i], real edges start at off[i]+1.
__global__ void k_scan_c() {
    __shared__ int warp_sums[32];
    __shared__ int s_blkoff;
    int tid = threadIdx.x, lane = tid & 31, wid = tid >> 5;
    if (wid == 0) {
        int ssum = 0;
        for (int j = lane; j < blockIdx.x; j += 32) ssum += g_blk[j];
        #pragma unroll
        for (int d = 16; d; d >>= 1) ssum += __shfl_xor_sync(0xFFFFFFFFu, ssum, d);
        if (lane == 0) s_blkoff = ssum;
    }
    int i = blockIdx.x * 1024 + tid;
    int v = (i < N_NODES) ? g_cnt[i] : 0;
    int x = v;
    #pragma unroll
    for (int d = 1; d < 32; d <<= 1) {
        int y = __shfl_up_sync(0xFFFFFFFFu, x, d);
        if (lane >= d) x += y;
    }
    if (lane == 31) warp_sums[wid] = x;
    __syncthreads();
    if (wid == 0) {
        int y = warp_sums[lane];
        #pragma unroll
        for (int d = 1; d < 32; d <<= 1) {
            int z = __shfl_up_sync(0xFFFFFFFFu, y, d);
            if (lane >= d) y += z;
        }
        warp_sums[lane] = y;
    }
    __syncthreads();
    if (i < N_NODES) {
        int excl = x - v + (wid ? warp_sums[wid - 1] : 0) + s_blkoff + i;
        g_off[i] = excl;
        g_csr_src[excl] = i;       // self loop in first slot
        g_cursor[i] = excl + 1;
    }
    if (i == 0) g_off[N_NODES] = E_TOT;
}

__global__ void k_scatter(const int* __restrict__ ei) {
    int e = blockIdx.x * blockDim.x + threadIdx.x;
    if (e >= N_EDGES) return;
    int src = ei[e], dst = ei[N_EDGES + e];
    int pos = atomicAdd(&g_cursor[dst], 1);
    g_csr_src[pos] = src;
}

// ---------------- layer 1: node transform, 32 nodes/block -------------------
__global__ void k_node1(const float* __restrict__ x, const int* __restrict__ tids,
                        const float* __restrict__ temb, const float* __restrict__ W1,
                        const float* __restrict__ as1, const float* __restrict__ ad1) {
    __shared__ float sW[21 * 64];
    __shared__ float sxin[4][21];
    int t = threadIdx.x;
    for (int i = t; i < 21 * 64; i += 256) sW[i] = W1[i];
    int nl = t >> 6, c = t & 63;
    #pragma unroll 1
    for (int it = 0; it < 8; ++it) {
        int node = blockIdx.x * 32 + it * 4 + nl;
        __syncthreads();
        if (node < N_NODES && c < 21)
            sxin[nl][c] = (c < 5) ? x[node * 5 + c] : temb[tids[node] * 16 + (c - 5)];
        __syncthreads();
        if (node >= N_NODES) continue;
        float h = 0.f;
        #pragma unroll
        for (int k = 0; k < 21; k++) h += sxin[nl][k] * sW[k * 64 + c];
        g_h1[node * 64 + c] = __float2half_rn(h);
        int head = c >> 5;
        float ps = h * as1[c], pd = h * ad1[c];
        #pragma unroll
        for (int d = 16; d; d >>= 1) {
            ps += __shfl_xor_sync(0xFFFFFFFFu, ps, d);
            pd += __shfl_xor_sync(0xFFFFFFFFu, pd, d);
        }
        if ((c & 31) == 0) {
            g_al1[node * 4 + head]     = ps;
            g_al1[node * 4 + 2 + head] = pd;
        }
    }
}

// ---------------- layer 1 aggregation: transposed gather --------------------
// Lane = (g = lane>>3, s = lane&7). Lane owns channels [8s, 8s+8) for edge
// slot g of each 4-edge group. One LDG.128 covers 4 edges' worth of features.
__global__ void k_agg1(const float* __restrict__ b1) {
    int w = (blockIdx.x * blockDim.x + threadIdx.x) >> 5;
    int lane = threadIdx.x & 31;
    if (w >= N_NODES) return;
    int dst = w;
    int g = lane >> 3, s = lane & 7;
    int woff = g + ((s >= 4) ? 16 : 0);
    float ald0 = g_al1[dst * 4 + 2], ald1 = g_al1[dst * 4 + 3];
    int beg = g_off[dst], end = g_off[dst + 1];
    float acc[8];
    #pragma unroll
    for (int k = 0; k < 8; k++) acc[k] = 0.f;
    float sw0 = 0.f, sw1 = 0.f;
    for (int base = beg; base < end; base += 32) {
        int K = end - base; K = (K > 32) ? 32 : K;
        int myidx = 0; float w0 = 0.f, w1 = 0.f;
        if (lane < K) {
            myidx = __ldg(&g_csr_src[base + lane]);
            float4 a = *reinterpret_cast<const float4*>(&g_al1[myidx * 4]);
            float e0 = a.x + ald0; e0 = (e0 > 0.f) ? e0 : NEG_SLOPE * e0;
            float e1 = a.y + ald1; e1 = (e1 > 0.f) ? e1 : NEG_SLOPE * e1;
            w0 = __expf(e0); w1 = __expf(e1);
            sw0 += w0; sw1 += w1;
        }
        // half 0 (edges 0..15): u[l<16]=w0[l], u[l>=16]=w1[l-16]
        {
            float tlo = __shfl_sync(0xFFFFFFFFu, w1, lane & 15);
            float u = (lane < 16) ? w0 : tlo;
            int se = K; se = (se > 16) ? 16 : se;
            for (int jj = 0; jj < se; jj += 4) {
                int sidx = __shfl_sync(0xFFFFFFFFu, myidx, jj + g);
                float wsv = __shfl_sync(0xFFFFFFFFu, u, jj + woff);
                uint4 hv = *reinterpret_cast<const uint4*>(&g_h1[sidx * 64 + s * 8]);
                float2 f0 = __half22float2(*reinterpret_cast<__half2*>(&hv.x));
                float2 f1 = __half22float2(*reinterpret_cast<__half2*>(&hv.y));
                float2 f2 = __half22float2(*reinterpret_cast<__half2*>(&hv.z));
                float2 f3 = __half22float2(*reinterpret_cast<__half2*>(&hv.w));
                acc[0] += wsv * f0.x; acc[1] += wsv * f0.y;
                acc[2] += wsv * f1.x; acc[3] += wsv * f1.y;
                acc[4] += wsv * f2.x; acc[5] += wsv * f2.y;
                acc[6] += wsv * f3.x; acc[7] += wsv * f3.y;
            }
        }
        // half 1 (edges 16..31): u2[l<16]=w0[16+l], u2[l>=16]=w1[l]
        if (K > 16) {
            float thi = __shfl_sync(0xFFFFFFFFu, w0, 16 + (lane & 15));
            float u2 = (lane < 16) ? thi : w1;
            int se = K - 16;
            for (int jj = 0; jj < se; jj += 4) {
                int sidx = __shfl_sync(0xFFFFFFFFu, myidx, 16 + jj + g);
                float wsv = __shfl_sync(0xFFFFFFFFu, u2, jj + woff);
                uint4 hv = *reinterpret_cast<const uint4*>(&g_h1[sidx * 64 + s * 8]);
                float2 f0 = __half22float2(*reinterpret_cast<__half2*>(&hv.x));
                float2 f1 = __half22float2(*reinterpret_cast<__half2*>(&hv.y));
                float2 f2 = __half22float2(*reinterpret_cast<__half2*>(&hv.z));
                float2 f3 = __half22float2(*reinterpret_cast<__half2*>(&hv.w));
                acc[0] += wsv * f0.x; acc[1] += wsv * f0.y;
                acc[2] += wsv * f1.x; acc[3] += wsv * f1.y;
                acc[4] += wsv * f2.x; acc[5] += wsv * f2.y;
                acc[6] += wsv * f3.x; acc[7] += wsv * f3.y;
            }
        }
    }
    // reduce across the 4 edge-slot groups
    #pragma unroll
    for (int k = 0; k < 8; k++) {
        acc[k] += __shfl_xor_sync(0xFFFFFFFFu, acc[k], 8);
        acc[k] += __shfl_xor_sync(0xFFFFFFFFu, acc[k], 16);
    }
    // softmax denominators
    #pragma unroll
    for (int d = 16; d; d >>= 1) {
        sw0 += __shfl_xor_sync(0xFFFFFFFFu, sw0, d);
        sw1 += __shfl_xor_sync(0xFFFFFFFFu, sw1, d);
    }
    float inv = 1.f / (((s >= 4) ? sw1 : sw0) + 1e-16f);
    if (g == 0) {
        float4 bA = *reinterpret_cast<const float4*>(&b1[8 * s]);
        float4 bB = *reinterpret_cast<const float4*>(&b1[8 * s + 4]);
        float4 o0, o1;
        o0.x = fmaxf(acc[0] * inv + bA.x, 0.f);
        o0.y = fmaxf(acc[1] * inv + bA.y, 0.f);
        o0.z = fmaxf(acc[2] * inv + bA.z, 0.f);
        o0.w = fmaxf(acc[3] * inv + bA.w, 0.f);
        o1.x = fmaxf(acc[4] * inv + bB.x, 0.f);
        o1.y = fmaxf(acc[5] * inv + bB.y, 0.f);
        o1.z = fmaxf(acc[6] * inv + bB.z, 0.f);
        o1.w = fmaxf(acc[7] * inv + bB.w, 0.f);
        *reinterpret_cast<float4*>(&g_hin2[dst * 64 + 8 * s])     = o0;
        *reinterpret_cast<float4*>(&g_hin2[dst * 64 + 8 * s + 4]) = o1;
    }
}

// ---------------- layer 2: node transform, 32 nodes/block -------------------
__global__ void k_node2(const float* __restrict__ W2,
                        const float* __restrict__ as2, const float* __restrict__ ad2) {
    __shared__ float sW[64 * 64];
    __shared__ float shin[4][64];
    __shared__ float s_part[4][2][2];
    int t = threadIdx.x;
    for (int i = t; i < 64 * 64; i += 256) sW[i] = W2[i];
    int nl = t >> 6, c = t & 63;
    #pragma unroll 1
    for (int it = 0; it < 8; ++it) {
        int node = blockIdx.x * 32 + it * 4 + nl;
        __syncthreads();
        if (node < N_NODES) shin[nl][c] = g_hin2[node * 64 + c];
        __syncthreads();
        if (node >= N_NODES) continue;
        float h = 0.f;
        #pragma unroll
        for (int k = 0; k < 64; k++) h += shin[nl][k] * sW[k * 64 + c];
        g_h2[node * 64 + c] = __float2half_rn(h);
        float ps = h * as2[c], pd = h * ad2[c];
        #pragma unroll
        for (int d = 16; d; d >>= 1) {
            ps += __shfl_xor_sync(0xFFFFFFFFu, ps, d);
            pd += __shfl_xor_sync(0xFFFFFFFFu, pd, d);
        }
        if ((c & 31) == 0) { s_part[nl][c >> 5][0] = ps; s_part[nl][c >> 5][1] = pd; }
        __syncthreads();
        if (c == 0) {
            g_al2[node * 2 + 0] = s_part[nl][0][0] + s_part[nl][1][0];
            g_al2[node * 2 + 1] = s_part[nl][0][1] + s_part[nl][1][1];
        }
    }
}

// ---------------- layer 2 aggregation (transposed) + LayerNorm --------------
__global__ void k_agg2(const float* __restrict__ b2, const float* __restrict__ gamma,
                       const float* __restrict__ beta, float* __restrict__ out) {
    int w = (blockIdx.x * blockDim.x + threadIdx.x) >> 5;
    int lane = threadIdx.x & 31;
    if (w >= N_NODES) return;
    int dst = w;
    int g = lane >> 3, s = lane & 7;
    float ald = g_al2[dst * 2 + 1];
    int beg = g_off[dst], end = g_off[dst + 1];
    float acc[8];
    #pragma unroll
    for (int k = 0; k < 8; k++) acc[k] = 0.f;
    float sw = 0.f;
    for (int base = beg; base < end; base += 32) {
        int K = end - base; K = (K > 32) ? 32 : K;
        int myidx = 0; float w0 = 0.f;
        if (lane < K) {
            myidx = __ldg(&g_csr_src[base + lane]);
            float a = __ldg(&g_al2[myidx * 2]);
            float e = a + ald; e = (e > 0.f) ? e : NEG_SLOPE * e;
            w0 = __expf(e);
            sw += w0;
        }
        for (int jj = 0; jj < K; jj += 4) {
            int el = jj + g;
            int sidx = __shfl_sync(0xFFFFFFFFu, myidx, el);
            float wsv = __shfl_sync(0xFFFFFFFFu, w0, el);
            uint4 hv = *reinterpret_cast<const uint4*>(&g_h2[sidx * 64 + s * 8]);
            float2 f0 = __half22float2(*reinterpret_cast<__half2*>(&hv.x));
            float2 f1 = __half22float2(*reinterpret_cast<__half2*>(&hv.y));
            float2 f2 = __half22float2(*reinterpret_cast<__half2*>(&hv.z));
            float2 f3 = __half22float2(*reinterpret_cast<__half2*>(&hv.w));
            acc[0] += wsv * f0.x; acc[1] += wsv * f0.y;
            acc[2] += wsv * f1.x; acc[3] += wsv * f1.y;
            acc[4] += wsv * f2.x; acc[5] += wsv * f2.y;
            acc[6] += wsv * f3.x; acc[7] += wsv * f3.y;
        }
    }
    #pragma unroll
    for (int k = 0; k < 8; k++) {
        acc[k] += __shfl_xor_sync(0xFFFFFFFFu, acc[k], 8);
        acc[k] += __shfl_xor_sync(0xFFFFFFFFu, acc[k], 16);
    }
    #pragma unroll
    for (int d = 16; d; d >>= 1) sw += __shfl_xor_sync(0xFFFFFFFFu, sw, d);
    float inv = 1.f / (sw + 1e-16f);
    float4 bA = *reinterpret_cast<const float4*>(&b2[8 * s]);
    float4 bB = *reinterpret_cast<const float4*>(&b2[8 * s + 4]);
    float r[8];
    r[0] = acc[0] * inv + bA.x; r[1] = acc[1] * inv + bA.y;
    r[2] = acc[2] * inv + bA.z; r[3] = acc[3] * inv + bA.w;
    r[4] = acc[4] * inv + bB.x; r[5] = acc[5] * inv + bB.y;
    r[6] = acc[6] * inv + bB.z; r[7] = acc[7] * inv + bB.w;
    // LayerNorm over 64 channels (8 per lane, reduce across s bits 1|2|4)
    float sum = 0.f;
    #pragma unroll
    for (int k = 0; k < 8; k++) sum += r[k];
    sum += __shfl_xor_sync(0xFFFFFFFFu, sum, 1);
    sum += __shfl_xor_sync(0xFFFFFFFFu, sum, 2);
    sum += __shfl_xor_sync(0xFFFFFFFFu, sum, 4);
    float mean = sum * (1.f / 64.f);
    float sq = 0.f;
    float dch[8];
    #pragma unroll
    for (int k = 0; k < 8; k++) { dch[k] = r[k] - mean; sq += dch[k] * dch[k]; }
    sq += __shfl_xor_sync(0xFFFFFFFFu, sq, 1);
    sq += __shfl_xor_sync(0xFFFFFFFFu, sq, 2);
    sq += __shfl_xor_sync(0xFFFFFFFFu, sq, 4);
    float rstd = rsqrtf(sq * (1.f / 64.f) + 1e-5f);
    if (g == 0) {
        float4 gA = *reinterpret_cast<const float4*>(&gamma[8 * s]);
        float4 gB = *reinterpret_cast<const float4*>(&gamma[8 * s + 4]);
        float4 tA = *reinterpret_cast<const float4*>(&beta[8 * s]);
        float4 tB = *reinterpret_cast<const float4*>(&beta[8 * s + 4]);
        float4 o0, o1;
        o0.x = dch[0] * rstd * gA.x + tA.x;
        o0.y = dch[1] * rstd * gA.y + tA.y;
        o0.z = dch[2] * rstd * gA.z + tA.z;
        o0.w = dch[3] * rstd * gA.w + tA.w;
        o1.x = dch[4] * rstd * gB.x + tB.x;
        o1.y = dch[5] * rstd * gB.y + tB.y;
        o1.z = dch[6] * rstd * gB.z + tB.z;
        o1.w = dch[7] * rstd * gB.w + tB.w;
        *reinterpret_cast<float4*>(&out[dst * 64 + 8 * s])     = o0;
        *reinterpret_cast<float4*>(&out[dst * 64 + 8 * s + 4]) = o1;
    }
}

// ---------------- launch ----------------------------------------------------
extern "C" void kernel_launch(void* const* d_in, const int* in_sizes, int n_in,
                              void* d_out, int out_size) {
    const float *x = nullptr, *temb = nullptr, *W1 = nullptr, *W2 = nullptr;
    const int *ei = nullptr, *tids = nullptr;
    const float* v64[8] = {nullptr};
    int n64 = 0;
    for (int i = 0; i < n_in; i++) {
        switch (in_sizes[i]) {
            case 500000:  x    = (const float*)d_in[i]; break;
            case 6400000: ei   = (const int*)d_in[i];   break;
            case 100000:  tids = (const int*)d_in[i];   break;
            case 128:     temb = (const float*)d_in[i]; break;
            case 1344:    W1   = (const float*)d_in[i]; break;
            case 4096:    W2   = (const float*)d_in[i]; break;
            case 64:      if (n64 < 8) v64[n64++] = (const float*)d_in[i]; break;
            default: break;
        }
    }
    const float* as1 = v64[0]; const float* ad1 = v64[1]; const float* b1 = v64[2];
    const float* as2 = v64[3]; const float* ad2 = v64[4]; const float* b2 = v64[5];
    const float* gamma = v64[6]; const float* beta = v64[7];
    float* out = (float*)d_out;

    k_init   <<<(N_NODES + 255) / 256, 256>>>();
    k_hist   <<<(N_EDGES + 255) / 256, 256>>>(ei);
    k_scan_a <<<N_TILES, 1024>>>();
    k_scan_c <<<N_TILES, 1024>>>();
    k_scatter<<<(N_EDGES + 255) / 256, 256>>>(ei);
    k_node1  <<<(N_NODES + 31) / 32, 256>>>(x, tids, temb, W1, as1, ad1);
    k_agg1   <<<(N_NODES + 7) / 8, 256>>>(b1);
    k_node2  <<<(N_NODES + 31) / 32, 256>>>(W2, as2, ad2);
    k_agg2   <<<(N_NODES + 7) / 8, 256>>>(b2, gamma, beta, out);
}

// round 10
// speedup vs baseline: 1.5780x; 1.5780x over previous
#include <cuda_runtime.h>
#include <cuda_fp16.h>
#include <cuda_bf16.h>

#define N_NODES 100000
#define N_EDGES 3200000
#define E_TOT   (N_EDGES + N_NODES)
#define NEG_SLOPE 0.2f
#define N_TILES 98   // ceil(100000 / 1024)

// ---------------- device scratch (allocation-free contract) ----------------
__device__ int g_cnt[N_NODES];
__device__ int g_off[N_NODES + 1];
__device__ int g_cursor[N_NODES];
__device__ int g_csr_src[E_TOT];
__device__ int g_blk[N_TILES];

__device__ __align__(16) __half g_h1[N_NODES * 64];  // layer-1 features (half gather table)
__device__ __align__(16) float g_al1[N_NODES * 4];   // [als0, als1, ald0, ald1]
__device__ __align__(16) float g_hin2[N_NODES * 64]; // relu(layer-1 out), fp32 for matmul
__device__ __align__(16) __half g_h2[N_NODES * 64];  // layer-2 features (half gather table)
__device__ __align__(8)  float g_al2[N_NODES * 2];   // [als, ald]

// ---------------- CSR build ----------------
__global__ void k_init() {
    int i = blockIdx.x * blockDim.x + threadIdx.x;
    if (i < N_NODES) g_cnt[i] = 0;
}

__global__ void k_hist(const int* __restrict__ ei) {
    int e = blockIdx.x * blockDim.x + threadIdx.x;
    if (e < N_EDGES) atomicAdd(&g_cnt[ei[N_EDGES + e]], 1);   // dst row
}

// phase A: per-tile (1024) sums
__global__ void k_scan_a() {
    __shared__ int ws[32];
    int tid = threadIdx.x, lane = tid & 31, wid = tid >> 5;
    int i = blockIdx.x * 1024 + tid;
    int v = (i < N_NODES) ? g_cnt[i] : 0;
    #pragma unroll
    for (int d = 16; d; d >>= 1) v += __shfl_xor_sync(0xFFFFFFFFu, v, d);
    if (lane == 0) ws[wid] = v;
    __syncthreads();
    if (wid == 0) {
        int y = ws[lane];
        #pragma unroll
        for (int d = 16; d; d >>= 1) y += __shfl_xor_sync(0xFFFFFFFFu, y, d);
        if (lane == 0) g_blk[blockIdx.x] = y;
    }
}

// phase C: per-tile rescan + inline tile-offset + self-loop emission
// off[i] = exclusive_scan(cnt)[i] + i ; self-loop in slot off[i], edges after.
__global__ void k_scan_c() {
    __shared__ int warp_sums[32];
    __shared__ int s_blkoff;
    int tid = threadIdx.x, lane = tid & 31, wid = tid >> 5;
    if (wid == 0) {
        int ssum = 0;
        for (int j = lane; j < blockIdx.x; j += 32) ssum += g_blk[j];
        #pragma unroll
        for (int d = 16; d; d >>= 1) ssum += __shfl_xor_sync(0xFFFFFFFFu, ssum, d);
        if (lane == 0) s_blkoff = ssum;
    }
    int i = blockIdx.x * 1024 + tid;
    int v = (i < N_NODES) ? g_cnt[i] : 0;
    int x = v;
    #pragma unroll
    for (int d = 1; d < 32; d <<= 1) {
        int y = __shfl_up_sync(0xFFFFFFFFu, x, d);
        if (lane >= d) x += y;
    }
    if (lane == 31) warp_sums[wid] = x;
    __syncthreads();
    if (wid == 0) {
        int y = warp_sums[lane];
        #pragma unroll
        for (int d = 1; d < 32; d <<= 1) {
            int z = __shfl_up_sync(0xFFFFFFFFu, y, d);
            if (lane >= d) y += z;
        }
        warp_sums[lane] = y;
    }
    __syncthreads();
    if (i < N_NODES) {
        int excl = x - v + (wid ? warp_sums[wid - 1] : 0) + s_blkoff + i;
        g_off[i] = excl;
        g_csr_src[excl] = i;       // self loop in first slot
        g_cursor[i] = excl + 1;
    }
    if (i == 0) g_off[N_NODES] = E_TOT;
}

__global__ void k_scatter(const int* __restrict__ ei) {
    int e = blockIdx.x * blockDim.x + threadIdx.x;
    if (e >= N_EDGES) return;
    int src = ei[e], dst = ei[N_EDGES + e];
    int pos = atomicAdd(&g_cursor[dst], 1);
    g_csr_src[pos] = src;
}

// ---------------- layer 1: node transform, 32 nodes/block -------------------
__global__ void k_node1(const float* __restrict__ x, const int* __restrict__ tids,
                        const float* __restrict__ temb, const float* __restrict__ W1,
                        const float* __restrict__ as1, const float* __restrict__ ad1) {
    __shared__ float sW[21 * 64];
    __shared__ float sxin[4][21];
    int t = threadIdx.x;
    for (int i = t; i < 21 * 64; i += 256) sW[i] = W1[i];
    int nl = t >> 6, c = t & 63;
    #pragma unroll 1
    for (int it = 0; it < 8; ++it) {
        int node = blockIdx.x * 32 + it * 4 + nl;
        __syncthreads();
        if (node < N_NODES && c < 21)
            sxin[nl][c] = (c < 5) ? x[node * 5 + c] : temb[tids[node] * 16 + (c - 5)];
        __syncthreads();
        if (node >= N_NODES) continue;
        float h = 0.f;
        #pragma unroll
        for (int k = 0; k < 21; k++) h += sxin[nl][k] * sW[k * 64 + c];
        g_h1[node * 64 + c] = __float2half_rn(h);
        int head = c >> 5;
        float ps = h * as1[c], pd = h * ad1[c];
        #pragma unroll
        for (int d = 16; d; d >>= 1) {
            ps += __shfl_xor_sync(0xFFFFFFFFu, ps, d);
            pd += __shfl_xor_sync(0xFFFFFFFFu, pd, d);
        }
        if ((c & 31) == 0) {
            g_al1[node * 4 + head]     = ps;
            g_al1[node * 4 + 2 + head] = pd;
        }
    }
}

// ---------------- layer 1 aggregation: warp/dst, shuffle-batched (R8) -------
// Lane l owns channels [2l, 2l+1]; lanes 0-15 = head0, 16-31 = head1.
__global__ void k_agg1(const float* __restrict__ b1) {
    int w = (blockIdx.x * blockDim.x + threadIdx.x) >> 5;
    int lane = threadIdx.x & 31;
    if (w >= N_NODES) return;
    int dst = w;
    float ald0 = g_al1[dst * 4 + 2], ald1 = g_al1[dst * 4 + 3];
    int beg = g_off[dst], end = g_off[dst + 1];
    float2 acc = make_float2(0.f, 0.f);
    float sw0 = 0.f, sw1 = 0.f;
    for (int base = beg; base < end; base += 32) {
        int K = end - base; K = (K > 32) ? 32 : K;
        int myidx = 0; float w0 = 0.f, w1 = 0.f;
        if (lane < K) {
            myidx = __ldg(&g_csr_src[base + lane]);
            float4 a = *reinterpret_cast<const float4*>(&g_al1[myidx * 4]);
            float e0 = a.x + ald0; e0 = (e0 > 0.f) ? e0 : NEG_SLOPE * e0;
            float e1 = a.y + ald1; e1 = (e1 > 0.f) ? e1 : NEG_SLOPE * e1;
            w0 = __expf(e0); w1 = __expf(e1);
            sw0 += w0; sw1 += w1;
        }
        int j = 0;
        for (; j + 4 <= K; j += 4) {
            int s0 = __shfl_sync(0xFFFFFFFFu, myidx, j);
            int s1 = __shfl_sync(0xFFFFFFFFu, myidx, j + 1);
            int s2 = __shfl_sync(0xFFFFFFFFu, myidx, j + 2);
            int s3 = __shfl_sync(0xFFFFFFFFu, myidx, j + 3);
            __half2 h0 = __ldg(reinterpret_cast<const __half2*>(&g_h1[s0 * 64 + 2 * lane]));
            __half2 h1 = __ldg(reinterpret_cast<const __half2*>(&g_h1[s1 * 64 + 2 * lane]));
            __half2 h2 = __ldg(reinterpret_cast<const __half2*>(&g_h1[s2 * 64 + 2 * lane]));
            __half2 h3 = __ldg(reinterpret_cast<const __half2*>(&g_h1[s3 * 64 + 2 * lane]));
            float2 f0 = __half22float2(h0);
            float2 f1 = __half22float2(h1);
            float2 f2 = __half22float2(h2);
            float2 f3 = __half22float2(h3);
            float wa, wb, ws;
            wa = __shfl_sync(0xFFFFFFFFu, w0, j);     wb = __shfl_sync(0xFFFFFFFFu, w1, j);
            ws = (lane < 16) ? wa : wb; acc.x += ws * f0.x; acc.y += ws * f0.y;
            wa = __shfl_sync(0xFFFFFFFFu, w0, j + 1); wb = __shfl_sync(0xFFFFFFFFu, w1, j + 1);
            ws = (lane < 16) ? wa : wb; acc.x += ws * f1.x; acc.y += ws * f1.y;
            wa = __shfl_sync(0xFFFFFFFFu, w0, j + 2); wb = __shfl_sync(0xFFFFFFFFu, w1, j + 2);
            ws = (lane < 16) ? wa : wb; acc.x += ws * f2.x; acc.y += ws * f2.y;
            wa = __shfl_sync(0xFFFFFFFFu, w0, j + 3); wb = __shfl_sync(0xFFFFFFFFu, w1, j + 3);
            ws = (lane < 16) ? wa : wb; acc.x += ws * f3.x; acc.y += ws * f3.y;
        }
        for (; j < K; ++j) {
            int s = __shfl_sync(0xFFFFFFFFu, myidx, j);
            float wa = __shfl_sync(0xFFFFFFFFu, w0, j);
            float wb = __shfl_sync(0xFFFFFFFFu, w1, j);
            float ws = (lane < 16) ? wa : wb;
            float2 f = __half22float2(
                __ldg(reinterpret_cast<const __half2*>(&g_h1[s * 64 + 2 * lane])));
            acc.x += ws * f.x; acc.y += ws * f.y;
        }
    }
    #pragma unroll
    for (int d = 16; d; d >>= 1) {
        sw0 += __shfl_xor_sync(0xFFFFFFFFu, sw0, d);
        sw1 += __shfl_xor_sync(0xFFFFFFFFu, sw1, d);
    }
    float inv = 1.f / (((lane < 16) ? sw0 : sw1) + 1e-16f);
    float r0 = acc.x * inv + b1[2 * lane];
    float r1 = acc.y * inv + b1[2 * lane + 1];
    float2 o = make_float2(fmaxf(r0, 0.f), fmaxf(r1, 0.f));
    *reinterpret_cast<float2*>(&g_hin2[dst * 64 + 2 * lane]) = o;
}

// ---------------- layer 2: node transform, 32 nodes/block -------------------
__global__ void k_node2(const float* __restrict__ W2,
                        const float* __restrict__ as2, const float* __restrict__ ad2) {
    __shared__ float sW[64 * 64];
    __shared__ float shin[4][64];
    __shared__ float s_part[4][2][2];
    int t = threadIdx.x;
    for (int i = t; i < 64 * 64; i += 256) sW[i] = W2[i];
    int nl = t >> 6, c = t & 63;
    #pragma unroll 1
    for (int it = 0; it < 8; ++it) {
        int node = blockIdx.x * 32 + it * 4 + nl;
        __syncthreads();
        if (node < N_NODES) shin[nl][c] = g_hin2[node * 64 + c];
        __syncthreads();
        if (node >= N_NODES) continue;
        float h = 0.f;
        #pragma unroll
        for (int k = 0; k < 64; k++) h += shin[nl][k] * sW[k * 64 + c];
        g_h2[node * 64 + c] = __float2half_rn(h);
        float ps = h * as2[c], pd = h * ad2[c];
        #pragma unroll
        for (int d = 16; d; d >>= 1) {
            ps += __shfl_xor_sync(0xFFFFFFFFu, ps, d);
            pd += __shfl_xor_sync(0xFFFFFFFFu, pd, d);
        }
        if ((c & 31) == 0) { s_part[nl][c >> 5][0] = ps; s_part[nl][c >> 5][1] = pd; }
        __syncthreads();
        if (c == 0) {
            g_al2[node * 2 + 0] = s_part[nl][0][0] + s_part[nl][1][0];
            g_al2[node * 2 + 1] = s_part[nl][0][1] + s_part[nl][1][1];
        }
    }
}

// ---------------- layer 2 aggregation + bias + LayerNorm (R8) ---------------
__global__ void k_agg2(const float* __restrict__ b2, const float* __restrict__ gamma,
                       const float* __restrict__ beta, float* __restrict__ out) {
    int w = (blockIdx.x * blockDim.x + threadIdx.x) >> 5;
    int lane = threadIdx.x & 31;
    if (w >= N_NODES) return;
    int dst = w;
    float ald = g_al2[dst * 2 + 1];
    int beg = g_off[dst], end = g_off[dst + 1];
    float2 acc = make_float2(0.f, 0.f);
    float sw = 0.f;
    for (int base = beg; base < end; base += 32) {
        int K = end - base; K = (K > 32) ? 32 : K;
        int myidx = 0; float w0 = 0.f;
        if (lane < K) {
            myidx = __ldg(&g_csr_src[base + lane]);
            float a = __ldg(&g_al2[myidx * 2]);
            float e = a + ald; e = (e > 0.f) ? e : NEG_SLOPE * e;
            w0 = __expf(e);
            sw += w0;
        }
        int j = 0;
        for (; j + 4 <= K; j += 4) {
            int s0 = __shfl_sync(0xFFFFFFFFu, myidx, j);
            int s1 = __shfl_sync(0xFFFFFFFFu, myidx, j + 1);
            int s2 = __shfl_sync(0xFFFFFFFFu, myidx, j + 2);
            int s3 = __shfl_sync(0xFFFFFFFFu, myidx, j + 3);
            __half2 h0 = __ldg(reinterpret_cast<const __half2*>(&g_h2[s0 * 64 + 2 * lane]));
            __half2 h1 = __ldg(reinterpret_cast<const __half2*>(&g_h2[s1 * 64 + 2 * lane]));
            __half2 h2 = __ldg(reinterpret_cast<const __half2*>(&g_h2[s2 * 64 + 2 * lane]));
            __half2 h3 = __ldg(reinterpret_cast<const __half2*>(&g_h2[s3 * 64 + 2 * lane]));
            float2 f0 = __half22float2(h0);
            float2 f1 = __half22float2(h1);
            float2 f2 = __half22float2(h2);
            float2 f3 = __half22float2(h3);
            float ws;
            ws = __shfl_sync(0xFFFFFFFFu, w0, j);     acc.x += ws * f0.x; acc.y += ws * f0.y;
            ws = __shfl_sync(0xFFFFFFFFu, w0, j + 1); acc.x += ws * f1.x; acc.y += ws * f1.y;
            ws = __shfl_sync(0xFFFFFFFFu, w0, j + 2); acc.x += ws * f2.x; acc.y += ws * f2.y;
            ws = __shfl_sync(0xFFFFFFFFu, w0, j + 3); acc.x += ws * f3.x; acc.y += ws * f3.y;
        }
        for (; j < K; ++j) {
            int s = __shfl_sync(0xFFFFFFFFu, myidx, j);
            float ws = __shfl_sync(0xFFFFFFFFu, w0, j);
            float2 f = __half22float2(
                __ldg(reinterpret_cast<const __half2*>(&g_h2[s * 64 + 2 * lane])));
            acc.x += ws * f.x; acc.y += ws * f.y;
        }
    }
    #pragma unroll
    for (int d = 16; d; d >>= 1) sw += __shfl_xor_sync(0xFFFFFFFFu, sw, d);
    float inv = 1.f / (sw + 1e-16f);
    float r0 = acc.x * inv + b2[2 * lane];
    float r1 = acc.y * inv + b2[2 * lane + 1];
    float sum = r0 + r1;
    #pragma unroll
    for (int d = 16; d; d >>= 1) sum += __shfl_xor_sync(0xFFFFFFFFu, sum, d);
    float mean = sum * (1.f / 64.f);
    float d0 = r0 - mean, d1 = r1 - mean;
    float sq = d0 * d0 + d1 * d1;
    #pragma unroll
    for (int d = 16; d; d >>= 1) sq += __shfl_xor_sync(0xFFFFFFFFu, sq, d);
    float rstd = rsqrtf(sq * (1.f / 64.f) + 1e-5f);
    float2 o;
    o.x = d0 * rstd * gamma[2 * lane]     + beta[2 * lane];
    o.y = d1 * rstd * gamma[2 * lane + 1] + beta[2 * lane + 1];
    *reinterpret_cast<float2*>(&out[dst * 64 + 2 * lane]) = o;
}

// ---------------- launch ----------------------------------------------------
extern "C" void kernel_launch(void* const* d_in, const int* in_sizes, int n_in,
                              void* d_out, int out_size) {
    const float *x = nullptr, *temb = nullptr, *W1 = nullptr, *W2 = nullptr;
    const int *ei = nullptr, *tids = nullptr;
    const float* v64[8] = {nullptr};
    int n64 = 0;
    for (int i = 0; i < n_in; i++) {
        switch (in_sizes[i]) {
            case 500000:  x    = (const float*)d_in[i]; break;
            case 6400000: ei   = (const int*)d_in[i];   break;
            case 100000:  tids = (const int*)d_in[i];   break;
            case 128:     temb = (const float*)d_in[i]; break;
            case 1344:    W1   = (const float*)d_in[i]; break;
            case 4096:    W2   = (const float*)d_in[i]; break;
            case 64:      if (n64 < 8) v64[n64++] = (const float*)d_in[i]; break;
            default: break;
        }
    }
    const float* as1 = v64[0]; const float* ad1 = v64[1]; const float* b1 = v64[2];
    const float* as2 = v64[3]; const float* ad2 = v64[4]; const float* b2 = v64[5];
    const float* gamma = v64[6]; const float* beta = v64[7];
    float* out = (float*)d_out;

    k_init   <<<(N_NODES + 255) / 256, 256>>>();
    k_hist   <<<(N_EDGES + 255) / 256, 256>>>(ei);
    k_scan_a <<<N_TILES, 1024>>>();
    k_scan_c <<<N_TILES, 1024>>>();
    k_scatter<<<(N_EDGES + 255) / 256, 256>>>(ei);
    k_node1  <<<(N_NODES + 31) / 32, 256>>>(x, tids, temb, W1, as1, ad1);
    k_agg1   <<<(N_NODES + 7) / 8, 256>>>(b1);
    k_node2  <<<(N_NODES + 31) / 32, 256>>>(W2, as2, ad2);
    k_agg2   <<<(N_NODES + 7) / 8, 256>>>(b2, gamma, beta, out);
}